// round 2
// baseline (speedup 1.0000x reference)
#include <cuda_runtime.h>
#include <math.h>

// Problem constants (fixed by the reference)
#define BATCH   2
#define SEQ     2048
#define DMODEL  1024
#define NHEADS  16
#define DK      64
#define MROWS   (BATCH * SEQ)          // 4096

// Scratch (allocation-free rule: __device__ globals)
__device__ float g_q[BATCH * NHEADS * SEQ * DK];   // [B,H,S,dk]
__device__ float g_k[BATCH * NHEADS * SEQ * DK];
__device__ float g_v[BATCH * NHEADS * SEQ * DK];
__device__ float g_att[BATCH * SEQ * DMODEL];      // [B,S,D]

// ---------------------------------------------------------------------------
// SGEMM: C = A[M,K] @ B[K,N] + bias, fp32.
// SPLIT=1: scatter output into head-major [B,H,S,dk] layout.
// 128x128 block tile, BK=8, 256 threads, 8x8 per-thread micro tile.
// ---------------------------------------------------------------------------
template <int SPLIT>
__global__ __launch_bounds__(256)
void sgemm_bias(const float* __restrict__ A, const float* __restrict__ Bm,
                const float* __restrict__ bias, float* __restrict__ C,
                int M, int N, int K)
{
    __shared__ float As[8][128];
    __shared__ float Bs[8][128];

    const int tid = threadIdx.x;
    const int bm0 = blockIdx.y * 128;
    const int bn0 = blockIdx.x * 128;
    const int tr = (tid / 16) * 8;     // 0..120
    const int tc = (tid % 16) * 8;

    float acc[8][8];
#pragma unroll
    for (int i = 0; i < 8; i++)
#pragma unroll
        for (int j = 0; j < 8; j++) acc[i][j] = 0.f;

    const int arow = tid >> 1;               // 0..127
    const int acol = (tid & 1) * 4;          // 0 or 4
    const int brow = tid >> 5;               // 0..7
    const int bcol = (tid & 31) * 4;         // 0..124

    const float* Aptr = A + (size_t)(bm0 + arow) * K + acol;
    const float* Bptr = Bm + (size_t)brow * N + bn0 + bcol;

    for (int k0 = 0; k0 < K; k0 += 8) {
        float4 a = *(const float4*)(Aptr + k0);
        float4 b = *(const float4*)(Bptr + (size_t)k0 * N);

        As[acol + 0][arow] = a.x;
        As[acol + 1][arow] = a.y;
        As[acol + 2][arow] = a.z;
        As[acol + 3][arow] = a.w;
        *(float4*)&Bs[brow][bcol] = b;
        __syncthreads();

#pragma unroll
        for (int kk = 0; kk < 8; kk++) {
            float ar[8], br[8];
#pragma unroll
            for (int u = 0; u < 8; u++) ar[u] = As[kk][tr + u];
#pragma unroll
            for (int u = 0; u < 8; u++) br[u] = Bs[kk][tc + u];
#pragma unroll
            for (int i = 0; i < 8; i++)
#pragma unroll
                for (int j = 0; j < 8; j++)
                    acc[i][j] += ar[i] * br[j];
        }
        __syncthreads();
    }

#pragma unroll
    for (int i = 0; i < 8; i++) {
#pragma unroll
        for (int j = 0; j < 8; j++) {
            int m = bm0 + tr + i;
            int n = bn0 + tc + j;
            float v = acc[i][j] + bias[n];
            if (SPLIT) {
                // m = b*SEQ + s ; n = h*DK + d  -> [B,H,S,DK]
                int bb = m >> 11;           // /SEQ
                int s  = m & 2047;
                int hh = n >> 6;            // /DK
                int dd = n & 63;
                C[((((size_t)bb * NHEADS) + hh) * SEQ + s) * DK + dd] = v;
            } else {
                C[(size_t)m * N + n] = v;
            }
        }
    }
}

// ---------------------------------------------------------------------------
// Flash attention, causal. One block = 64 query rows of one (b,h);
// one thread = one query row. K/V tiles (32 x 64) staged in shared.
// q row + fp32 accumulator live in registers. Online softmax per tile.
// ---------------------------------------------------------------------------
__global__ __launch_bounds__(64)
void flash_attn(const float* __restrict__ Qm, const float* __restrict__ Km,
                const float* __restrict__ Vm, const float* __restrict__ pmask,
                float* __restrict__ O)
{
    __shared__ float Ks[32][64];
    __shared__ float Vs[32][64];
    __shared__ float pm[32];

    const int i  = threadIdx.x;            // query row within tile (0..63)
    const int q0 = blockIdx.x * 64;
    const int bh = blockIdx.y;             // b*NHEADS + h
    const int b  = bh >> 4;
    const int h  = bh & 15;
    const int qi = q0 + i;

    // Load q row into registers
    float q[DK];
    {
        const float4* qp = (const float4*)(Qm + ((size_t)bh * SEQ + qi) * DK);
#pragma unroll
        for (int u = 0; u < DK / 4; u++) {
            float4 t = qp[u];
            q[4*u+0] = t.x; q[4*u+1] = t.y; q[4*u+2] = t.z; q[4*u+3] = t.w;
        }
    }

    float acc[DK];
#pragma unroll
    for (int u = 0; u < DK; u++) acc[u] = 0.f;
    float mrun = -1e30f;
    float lrun = 0.f;

    const int ntiles = (q0 + 64 + 31) / 32;      // key tiles needed (causal)
    const int jrow = i >> 1;                     // 0..31
    const int jcol = (i & 1) * 32;               // 0 or 32

    for (int t = 0; t < ntiles; t++) {
        const int k0 = t * 32;
        {
            const float4* kp = (const float4*)(Km + ((size_t)bh * SEQ + k0 + jrow) * DK + jcol);
            const float4* vp = (const float4*)(Vm + ((size_t)bh * SEQ + k0 + jrow) * DK + jcol);
            float4* kd = (float4*)&Ks[jrow][jcol];
            float4* vd = (float4*)&Vs[jrow][jcol];
#pragma unroll
            for (int u = 0; u < 8; u++) {
                kd[u] = kp[u];
                vd[u] = vp[u];
            }
        }
        if (i < 32) pm[i] = pmask[(size_t)b * SEQ + k0 + i];
        __syncthreads();

        // scores for this thread's query row against 32 keys
        float s[32];
#pragma unroll
        for (int j = 0; j < 32; j++) {
            const float4* kr = (const float4*)Ks[j];
            float d0 = 0.f, d1 = 0.f, d2 = 0.f, d3 = 0.f;
#pragma unroll
            for (int u = 0; u < 16; u++) {
                float4 kv = kr[u];
                d0 += q[4*u+0] * kv.x;
                d1 += q[4*u+1] * kv.y;
                d2 += q[4*u+2] * kv.z;
                d3 += q[4*u+3] * kv.w;
            }
            int kj = k0 + j;
            float sc = (d0 + d1) + (d2 + d3);
            s[j] = sc * 0.125f + pm[j] + ((kj > qi) ? -1e9f : 0.f);
        }

        // online softmax update
        float mt = s[0];
#pragma unroll
        for (int j = 1; j < 32; j++) mt = fmaxf(mt, s[j]);
        float mnew  = fmaxf(mrun, mt);
        float alpha = __expf(mrun - mnew);
        lrun *= alpha;
#pragma unroll
        for (int u = 0; u < DK; u++) acc[u] *= alpha;

#pragma unroll
        for (int j = 0; j < 32; j++) {
            float p = __expf(s[j] - mnew);
            lrun += p;
            const float4* vr = (const float4*)Vs[j];
#pragma unroll
            for (int u = 0; u < 16; u++) {
                float4 vv = vr[u];
                acc[4*u+0] += p * vv.x;
                acc[4*u+1] += p * vv.y;
                acc[4*u+2] += p * vv.z;
                acc[4*u+3] += p * vv.w;
            }
        }
        mrun = mnew;
        __syncthreads();
    }

    const float inv = 1.f / lrun;
    float4* op = (float4*)(O + ((size_t)b * SEQ + qi) * DMODEL + h * DK);
#pragma unroll
    for (int u = 0; u < DK / 4; u++) {
        float4 r;
        r.x = acc[4*u+0] * inv;
        r.y = acc[4*u+1] * inv;
        r.z = acc[4*u+2] * inv;
        r.w = acc[4*u+3] * inv;
        op[u] = r;
    }
}

// ---------------------------------------------------------------------------
// Launch
// Inputs (metadata order): 0 query, 1 key, 2 value, 3 padding_mask,
// 4 lookahead_mask, 5 w_q, 6 w_k, 7 w_v, 8 w_out, 9 b_q, 10 b_k, 11 b_v,
// 12 b_out, 13 n_heads
// ---------------------------------------------------------------------------
extern "C" void kernel_launch(void* const* d_in, const int* in_sizes, int n_in,
                              void* d_out, int out_size)
{
    const float* query = (const float*)d_in[0];
    const float* key   = (const float*)d_in[1];
    const float* value = (const float*)d_in[2];
    const float* pmask = (const float*)d_in[3];
    const float* w_q   = (const float*)d_in[5];
    const float* w_k   = (const float*)d_in[6];
    const float* w_v   = (const float*)d_in[7];
    const float* w_out = (const float*)d_in[8];
    const float* b_q   = (const float*)d_in[9];
    const float* b_k   = (const float*)d_in[10];
    const float* b_v   = (const float*)d_in[11];
    const float* b_out = (const float*)d_in[12];
    float* out = (float*)d_out;

    float *pq, *pk, *pv, *patt;
    cudaGetSymbolAddress((void**)&pq,   g_q);
    cudaGetSymbolAddress((void**)&pk,   g_k);
    cudaGetSymbolAddress((void**)&pv,   g_v);
    cudaGetSymbolAddress((void**)&patt, g_att);

    dim3 gproj(DMODEL / 128, MROWS / 128);   // (8, 32)
    sgemm_bias<1><<<gproj, 256>>>(query, w_q, b_q, pq, MROWS, DMODEL, DMODEL);
    sgemm_bias<1><<<gproj, 256>>>(key,   w_k, b_k, pk, MROWS, DMODEL, DMODEL);
    sgemm_bias<1><<<gproj, 256>>>(value, w_v, b_v, pv, MROWS, DMODEL, DMODEL);

    dim3 gattn(SEQ / 64, BATCH * NHEADS);    // (32, 32)
    flash_attn<<<gattn, 64>>>(pq, pk, pv, pmask, patt);

    sgemm_bias<0><<<gproj, 256>>>(patt, w_out, b_out, out, MROWS, DMODEL, DMODEL);
}

// round 11
// speedup vs baseline: 1.5837x; 1.5837x over previous
#include <cuda_runtime.h>
#include <cuda_bf16.h>
#include <mma.h>
#include <math.h>
#include <stdint.h>

using namespace nvcuda;

// Problem constants (fixed by the reference)
#define BATCH   2
#define SEQ     2048
#define DMODEL  1024
#define NHEADS  16
#define DK      64
#define MROWS   (BATCH * SEQ)          // 4096
#define GK      1024
#define GN      1024

// Scratch (allocation-free rule: __device__ globals)
__device__ float g_q[BATCH * NHEADS * SEQ * DK];   // [B,H,S,dk]
__device__ float g_k[BATCH * NHEADS * SEQ * DK];
__device__ float g_v[BATCH * NHEADS * SEQ * DK];
__device__ float g_att[BATCH * SEQ * DMODEL];      // [B,S,D]

// ===========================================================================
// Tensor-core GEMM via wmma (HMMA path; tcgen05 is unavailable because the
// harness assembles through compute_103, which gates all sm_103a features).
// C[M,N] = A[M,K] @ W[K,N] + bias, fp32 in/out, bf16 hi/lo split (3 MMAs).
// CTA tile 128x128, K chunk 64, 256 threads = 8 warps, warp tile 32x64.
// SPLIT=1 scatters output to head-major [B,H,S,dk].
// ===========================================================================
#define BKC     64
#define LDA     72              // 64 + 8 pad (bf16 elems)
#define LDB     136             // 128 + 8 pad (bf16 elems)

// dynamic smem layout (bytes)
#define OFF_AHI  0
#define OFF_ALO  (128 * LDA * 2)                    // 18432
#define OFF_BHI  (2 * 128 * LDA * 2)                // 36864
#define OFF_BLO  (2 * 128 * LDA * 2 + BKC * LDB * 2)// 54272
#define GEMM_SMEM (2 * 128 * LDA * 2 + 2 * BKC * LDB * 2)  // 71680
// epilogue f32 tile overlays staging (65536 <= 71680), used after final sync
#define LDO      128

template <int SPLIT>
__global__ __launch_bounds__(256)
void gemm_tc(const float* __restrict__ A, const float* __restrict__ W,
             const float* __restrict__ bias, float* __restrict__ C)
{
    extern __shared__ char smem[];
    __nv_bfloat16* As_hi = (__nv_bfloat16*)(smem + OFF_AHI);
    __nv_bfloat16* As_lo = (__nv_bfloat16*)(smem + OFF_ALO);
    __nv_bfloat16* Bs_hi = (__nv_bfloat16*)(smem + OFF_BHI);
    __nv_bfloat16* Bs_lo = (__nv_bfloat16*)(smem + OFF_BLO);
    float*         Cs    = (float*)smem;

    const int tid = threadIdx.x;
    const int wid = tid >> 5;
    const int bm0 = blockIdx.y * 128;
    const int bn0 = blockIdx.x * 128;

    const int wm = (wid & 3) * 32;      // warp m offset (4 warps over m)
    const int wn = (wid >> 2) * 64;     // warp n offset (2 warps over n)

    wmma::fragment<wmma::accumulator, 16, 16, 16, float> acc[2][4];
#pragma unroll
    for (int i = 0; i < 2; i++)
#pragma unroll
        for (int j = 0; j < 4; j++) wmma::fill_fragment(acc[i][j], 0.0f);

    // staging maps
    const int a_row = tid >> 1;               // 0..127
    const int a_c0  = (tid & 1) * 32;         // 0 or 32
    const int b_k   = tid >> 2;               // 0..63
    const int b_c0  = (tid & 3) * 32;         // 0..96

    for (int k0 = 0; k0 < GK; k0 += BKC) {
        // ---- stage A[128 x 64] hi/lo
        {
            const float4* ap = (const float4*)(A + (size_t)(bm0 + a_row) * GK + k0 + a_c0);
            __nv_bfloat16* dh = As_hi + a_row * LDA + a_c0;
            __nv_bfloat16* dl = As_lo + a_row * LDA + a_c0;
#pragma unroll
            for (int u = 0; u < 8; u++) {
                float4 v = ap[u];
                float f[4] = {v.x, v.y, v.z, v.w};
#pragma unroll
                for (int j = 0; j < 4; j++) {
                    __nv_bfloat16 h = __float2bfloat16_rn(f[j]);
                    dh[u * 4 + j] = h;
                    dl[u * 4 + j] = __float2bfloat16_rn(f[j] - __bfloat162float(h));
                }
            }
        }
        // ---- stage B[64 x 128] hi/lo (row k, col n)
        {
            const float4* wp = (const float4*)(W + (size_t)(k0 + b_k) * GN + bn0 + b_c0);
            __nv_bfloat16* dh = Bs_hi + b_k * LDB + b_c0;
            __nv_bfloat16* dl = Bs_lo + b_k * LDB + b_c0;
#pragma unroll
            for (int u = 0; u < 8; u++) {
                float4 v = wp[u];
                float f[4] = {v.x, v.y, v.z, v.w};
#pragma unroll
                for (int j = 0; j < 4; j++) {
                    __nv_bfloat16 h = __float2bfloat16_rn(f[j]);
                    dh[u * 4 + j] = h;
                    dl[u * 4 + j] = __float2bfloat16_rn(f[j] - __bfloat162float(h));
                }
            }
        }
        __syncthreads();

        // ---- compute: 4 k-steps of 16
#pragma unroll
        for (int kk = 0; kk < 4; kk++) {
            wmma::fragment<wmma::matrix_a, 16, 16, 16, __nv_bfloat16, wmma::row_major> a_hi[2], a_lo[2];
#pragma unroll
            for (int i = 0; i < 2; i++) {
                const __nv_bfloat16* ap = As_hi + (wm + i * 16) * LDA + kk * 16;
                wmma::load_matrix_sync(a_hi[i], ap, LDA);
                wmma::load_matrix_sync(a_lo[i], As_lo + (wm + i * 16) * LDA + kk * 16, LDA);
            }
#pragma unroll
            for (int j = 0; j < 4; j++) {
                wmma::fragment<wmma::matrix_b, 16, 16, 16, __nv_bfloat16, wmma::row_major> b_hi, b_lo;
                wmma::load_matrix_sync(b_hi, Bs_hi + (kk * 16) * LDB + wn + j * 16, LDB);
                wmma::load_matrix_sync(b_lo, Bs_lo + (kk * 16) * LDB + wn + j * 16, LDB);
#pragma unroll
                for (int i = 0; i < 2; i++) {
                    wmma::mma_sync(acc[i][j], a_hi[i], b_hi, acc[i][j]);
                    wmma::mma_sync(acc[i][j], a_hi[i], b_lo, acc[i][j]);
                    wmma::mma_sync(acc[i][j], a_lo[i], b_hi, acc[i][j]);
                }
            }
        }
        __syncthreads();
    }

    // ---- epilogue: dump fragments to smem f32 tile, then bias + (scatter) store
#pragma unroll
    for (int i = 0; i < 2; i++)
#pragma unroll
        for (int j = 0; j < 4; j++)
            wmma::store_matrix_sync(Cs + (wm + i * 16) * LDO + wn + j * 16,
                                    acc[i][j], LDO, wmma::mem_row_major);
    __syncthreads();

    {
        const int row = tid >> 1;                 // 0..127
        const int c0  = (tid & 1) * 64;           // 0 or 64
        const int m   = bm0 + row;
        const float4* src = (const float4*)(Cs + row * LDO + c0);
#pragma unroll
        for (int u = 0; u < 16; u++) {
            float4 v = src[u];
            int n = bn0 + c0 + u * 4;
            v.x += bias[n + 0];
            v.y += bias[n + 1];
            v.z += bias[n + 2];
            v.w += bias[n + 3];
            if (SPLIT) {
                // m = b*SEQ + s ; n = h*DK + d -> [B,H,S,DK]; DK groups of 4 stay contiguous
                int bb = m >> 11, s = m & 2047;
                int hh = n >> 6,  dd = n & 63;
                *(float4*)&C[((((size_t)bb * NHEADS) + hh) * SEQ + s) * DK + dd] = v;
            } else {
                *(float4*)&C[(size_t)m * GN + n] = v;
            }
        }
    }
}

// ===========================================================================
// Flash attention, causal. 128 threads / block, 64 query rows:
// 2 lanes per row (each owns 32 of 64 dims), paired via shfl_xor(16).
// ===========================================================================
__global__ __launch_bounds__(128)
void flash_attn(const float* __restrict__ Qm, const float* __restrict__ Km,
                const float* __restrict__ Vm, const float* __restrict__ pmask,
                float* __restrict__ O)
{
    __shared__ float Ks[32][64];
    __shared__ float Vs[32][64];
    __shared__ float pm[32];

    const int tid = threadIdx.x;
    const int w   = tid >> 5;
    const int l   = tid & 31;
    const int r   = w * 16 + (l & 15);     // query row within tile (0..63)
    const int hh  = l >> 4;                // dim half (0/1)
    const int q0  = blockIdx.x * 64;
    const int bh  = blockIdx.y;
    const int b   = bh >> 4;
    const int h   = bh & 15;
    const int qi  = q0 + r;

    // q half-row into registers
    float q[32];
    {
        const float4* qp = (const float4*)(Qm + ((size_t)bh * SEQ + qi) * DK + hh * 32);
#pragma unroll
        for (int u = 0; u < 8; u++) {
            float4 t = qp[u];
            q[4*u+0] = t.x; q[4*u+1] = t.y; q[4*u+2] = t.z; q[4*u+3] = t.w;
        }
    }

    float acc[32];
#pragma unroll
    for (int u = 0; u < 32; u++) acc[u] = 0.f;
    float mrun = -1e30f;
    float lrun = 0.f;

    const int ntiles = (q0 + 64) / 32;

    for (int t = 0; t < ntiles; t++) {
        const int k0 = t * 32;
        // stage K/V tile (32x64) with 128 threads, 4 float4 each
        {
#pragma unroll
            for (int u = 0; u < 4; u++) {
                int f   = tid * 4 + u;          // 0..511
                int row = f >> 4;
                int c4  = (f & 15) * 4;
                *(float4*)&Ks[row][c4] =
                    *(const float4*)(Km + ((size_t)bh * SEQ + k0 + row) * DK + c4);
                *(float4*)&Vs[row][c4] =
                    *(const float4*)(Vm + ((size_t)bh * SEQ + k0 + row) * DK + c4);
            }
        }
        if (tid < 32) pm[tid] = pmask[(size_t)b * SEQ + k0 + tid];
        __syncthreads();

        // scores: partial dot over this lane's 32 dims, pair-sum via shfl
        float s[32];
#pragma unroll
        for (int j = 0; j < 32; j++) {
            const float4* kr = (const float4*)&Ks[j][hh * 32];
            float d0 = 0.f, d1 = 0.f, d2 = 0.f, d3 = 0.f;
#pragma unroll
            for (int u = 0; u < 8; u++) {
                float4 kv = kr[u];
                d0 += q[4*u+0] * kv.x;
                d1 += q[4*u+1] * kv.y;
                d2 += q[4*u+2] * kv.z;
                d3 += q[4*u+3] * kv.w;
            }
            float part = (d0 + d1) + (d2 + d3);
            float full = part + __shfl_xor_sync(0xffffffffu, part, 16);
            int kj = k0 + j;
            s[j] = full * 0.125f + pm[j] + ((kj > qi) ? -1e9f : 0.f);
        }

        // online softmax update (identical for both lanes of a pair)
        float mt = s[0];
#pragma unroll
        for (int j = 1; j < 32; j++) mt = fmaxf(mt, s[j]);
        float mnew  = fmaxf(mrun, mt);
        float alpha = __expf(mrun - mnew);
        lrun *= alpha;
#pragma unroll
        for (int u = 0; u < 32; u++) acc[u] *= alpha;

#pragma unroll
        for (int j = 0; j < 32; j++) {
            float p = __expf(s[j] - mnew);
            lrun += p;
            const float4* vr = (const float4*)&Vs[j][hh * 32];
#pragma unroll
            for (int u = 0; u < 8; u++) {
                float4 vv = vr[u];
                acc[4*u+0] += p * vv.x;
                acc[4*u+1] += p * vv.y;
                acc[4*u+2] += p * vv.z;
                acc[4*u+3] += p * vv.w;
            }
        }
        mrun = mnew;
        __syncthreads();
    }

    const float inv = 1.f / lrun;
    float4* op = (float4*)(O + ((size_t)b * SEQ + qi) * DMODEL + h * DK + hh * 32);
#pragma unroll
    for (int u = 0; u < 8; u++) {
        float4 rr;
        rr.x = acc[4*u+0] * inv;
        rr.y = acc[4*u+1] * inv;
        rr.z = acc[4*u+2] * inv;
        rr.w = acc[4*u+3] * inv;
        op[u] = rr;
    }
}

// ---------------------------------------------------------------------------
// Launch. Inputs: 0 query, 1 key, 2 value, 3 padding_mask, 4 lookahead_mask,
// 5 w_q, 6 w_k, 7 w_v, 8 w_out, 9 b_q, 10 b_k, 11 b_v, 12 b_out, 13 n_heads
// ---------------------------------------------------------------------------
extern "C" void kernel_launch(void* const* d_in, const int* in_sizes, int n_in,
                              void* d_out, int out_size)
{
    const float* query = (const float*)d_in[0];
    const float* key   = (const float*)d_in[1];
    const float* value = (const float*)d_in[2];
    const float* pmask = (const float*)d_in[3];
    const float* w_q   = (const float*)d_in[5];
    const float* w_k   = (const float*)d_in[6];
    const float* w_v   = (const float*)d_in[7];
    const float* w_out = (const float*)d_in[8];
    const float* b_q   = (const float*)d_in[9];
    const float* b_k   = (const float*)d_in[10];
    const float* b_v   = (const float*)d_in[11];
    const float* b_out = (const float*)d_in[12];
    float* out = (float*)d_out;

    float *pq, *pk, *pv, *patt;
    cudaGetSymbolAddress((void**)&pq,   g_q);
    cudaGetSymbolAddress((void**)&pk,   g_k);
    cudaGetSymbolAddress((void**)&pv,   g_v);
    cudaGetSymbolAddress((void**)&patt, g_att);

    cudaFuncSetAttribute(gemm_tc<0>, cudaFuncAttributeMaxDynamicSharedMemorySize, GEMM_SMEM);
    cudaFuncSetAttribute(gemm_tc<1>, cudaFuncAttributeMaxDynamicSharedMemorySize, GEMM_SMEM);

    dim3 gproj(GN / 128, MROWS / 128);   // (8, 32)
    gemm_tc<1><<<gproj, 256, GEMM_SMEM>>>(query, w_q, b_q, pq);
    gemm_tc<1><<<gproj, 256, GEMM_SMEM>>>(key,   w_k, b_k, pk);
    gemm_tc<1><<<gproj, 256, GEMM_SMEM>>>(value, w_v, b_v, pv);

    dim3 gattn(SEQ / 64, BATCH * NHEADS);    // (32, 32)
    flash_attn<<<gattn, 128>>>(pq, pk, pv, pmask, patt);

    gemm_tc<0><<<gproj, 256, GEMM_SMEM>>>(patt, w_out, b_out, out);
}

// round 14
// speedup vs baseline: 2.3228x; 1.4667x over previous
#include <cuda_runtime.h>
#include <cuda_bf16.h>
#include <mma.h>
#include <math.h>
#include <stdint.h>

using namespace nvcuda;

// Problem constants
#define BATCH   2
#define SEQ     2048
#define DMODEL  1024
#define NHEADS  16
#define DK      64
#define MROWS   (BATCH * SEQ)          // 4096
#define GK      1024
#define GN      1024
#define NELEM   (BATCH * SEQ * DMODEL) // 4194304
#define WELEM   (DMODEL * DMODEL)      // 1048576

// ---------------------------------------------------------------------------
// Scratch (__device__ globals; allocation-free rule)
// ---------------------------------------------------------------------------
__device__ __nv_bfloat16 g_aqh[NELEM], g_aql[NELEM];   // query input hi/lo [B,S,D]
__device__ __nv_bfloat16 g_akh[NELEM], g_akl[NELEM];   // key   input hi/lo
__device__ __nv_bfloat16 g_avh[NELEM], g_avl[NELEM];   // value input hi/lo
__device__ __nv_bfloat16 g_wqh[WELEM], g_wql[WELEM];   // weights hi/lo
__device__ __nv_bfloat16 g_wkh[WELEM], g_wkl[WELEM];
__device__ __nv_bfloat16 g_wvh[WELEM], g_wvl[WELEM];
__device__ __nv_bfloat16 g_woh[WELEM], g_wol[WELEM];
__device__ __nv_bfloat16 g_qh[NELEM],  g_ql[NELEM];    // Q proj, head-major [B,H,S,dk]
__device__ __nv_bfloat16 g_kh[NELEM],  g_kl[NELEM];    // K proj
__device__ __nv_bfloat16 g_vh[NELEM],  g_vl[NELEM];    // V proj
__device__ __nv_bfloat16 g_oh[NELEM],  g_ol[NELEM];    // attention out [B,S,D]

// ---------------------------------------------------------------------------
// fp32 -> bf16 hi/lo conversion (one pass, bandwidth-bound)
// ---------------------------------------------------------------------------
__global__ __launch_bounds__(256)
void cvt_hilo(const float4* __restrict__ src, __nv_bfloat16* __restrict__ hi,
              __nv_bfloat16* __restrict__ lo, int n4)
{
    int i = blockIdx.x * 256 + threadIdx.x;
    if (i >= n4) return;
    float4 v = src[i];
    float f[4] = {v.x, v.y, v.z, v.w};
    __nv_bfloat16 h[4], l[4];
#pragma unroll
    for (int j = 0; j < 4; j++) {
        h[j] = __float2bfloat16_rn(f[j]);
        l[j] = __float2bfloat16_rn(f[j] - __bfloat162float(h[j]));
    }
    ((__nv_bfloat162*)hi)[2*i+0] = __nv_bfloat162(h[0], h[1]);
    ((__nv_bfloat162*)hi)[2*i+1] = __nv_bfloat162(h[2], h[3]);
    ((__nv_bfloat162*)lo)[2*i+0] = __nv_bfloat162(l[0], l[1]);
    ((__nv_bfloat162*)lo)[2*i+1] = __nv_bfloat162(l[2], l[3]);
}

// ---------------------------------------------------------------------------
// Tensor-core GEMM (wmma/HMMA), pre-split bf16 hi/lo operands.
// C = A @ W + bias. CTA 128x128, BKC 64, 256 thr / 8 warps, warp tile 32x64.
// SPLIT=1: output as hi/lo bf16, scattered to head-major [B,H,S,dk].
// SPLIT=0: output fp32 row-major.
// ---------------------------------------------------------------------------
#define BKC  64
#define LDA  72
#define LDB  136
#define OFF_AHI  0
#define OFF_ALO  (128 * LDA * 2)
#define OFF_BHI  (2 * 128 * LDA * 2)
#define OFF_BLO  (2 * 128 * LDA * 2 + BKC * LDB * 2)
#define GEMM_SMEM (2 * 128 * LDA * 2 + 2 * BKC * LDB * 2)  // 71680
#define LDO  128

template <int SPLIT>
__global__ __launch_bounds__(256)
void gemm_tc(const __nv_bfloat16* __restrict__ Ah, const __nv_bfloat16* __restrict__ Al,
             const __nv_bfloat16* __restrict__ Wh, const __nv_bfloat16* __restrict__ Wl,
             const float* __restrict__ bias,
             float* __restrict__ Cf,
             __nv_bfloat16* __restrict__ Ch, __nv_bfloat16* __restrict__ Cl)
{
    extern __shared__ char smem[];
    __nv_bfloat16* As_hi = (__nv_bfloat16*)(smem + OFF_AHI);
    __nv_bfloat16* As_lo = (__nv_bfloat16*)(smem + OFF_ALO);
    __nv_bfloat16* Bs_hi = (__nv_bfloat16*)(smem + OFF_BHI);
    __nv_bfloat16* Bs_lo = (__nv_bfloat16*)(smem + OFF_BLO);
    float*         Cs    = (float*)smem;

    const int tid = threadIdx.x;
    const int wid = tid >> 5;
    const int bm0 = blockIdx.y * 128;
    const int bn0 = blockIdx.x * 128;
    const int wm = (wid & 3) * 32;
    const int wn = (wid >> 2) * 64;

    wmma::fragment<wmma::accumulator, 16, 16, 16, float> acc[2][4];
#pragma unroll
    for (int i = 0; i < 2; i++)
#pragma unroll
        for (int j = 0; j < 4; j++) wmma::fill_fragment(acc[i][j], 0.0f);

    const int a_row = tid >> 1;               // 0..127
    const int a_c0  = (tid & 1) * 32;
    const int b_k   = tid >> 2;               // 0..63
    const int b_c0  = (tid & 3) * 32;

    for (int k0 = 0; k0 < GK; k0 += BKC) {
        // pure-copy staging (4x uint4 per operand per matrix)
        {
            const uint4* sh = (const uint4*)(Ah + (size_t)(bm0 + a_row) * GK + k0 + a_c0);
            const uint4* sl = (const uint4*)(Al + (size_t)(bm0 + a_row) * GK + k0 + a_c0);
            uint4* dh = (uint4*)(As_hi + a_row * LDA + a_c0);
            uint4* dl = (uint4*)(As_lo + a_row * LDA + a_c0);
#pragma unroll
            for (int u = 0; u < 4; u++) { dh[u] = sh[u]; dl[u] = sl[u]; }
        }
        {
            const uint4* sh = (const uint4*)(Wh + (size_t)(k0 + b_k) * GN + bn0 + b_c0);
            const uint4* sl = (const uint4*)(Wl + (size_t)(k0 + b_k) * GN + bn0 + b_c0);
            uint4* dh = (uint4*)(Bs_hi + b_k * LDB + b_c0);
            uint4* dl = (uint4*)(Bs_lo + b_k * LDB + b_c0);
#pragma unroll
            for (int u = 0; u < 4; u++) { dh[u] = sh[u]; dl[u] = sl[u]; }
        }
        __syncthreads();

#pragma unroll
        for (int kk = 0; kk < 4; kk++) {
            wmma::fragment<wmma::matrix_a, 16, 16, 16, __nv_bfloat16, wmma::row_major> a_hi[2], a_lo[2];
#pragma unroll
            for (int i = 0; i < 2; i++) {
                wmma::load_matrix_sync(a_hi[i], As_hi + (wm + i * 16) * LDA + kk * 16, LDA);
                wmma::load_matrix_sync(a_lo[i], As_lo + (wm + i * 16) * LDA + kk * 16, LDA);
            }
#pragma unroll
            for (int j = 0; j < 4; j++) {
                wmma::fragment<wmma::matrix_b, 16, 16, 16, __nv_bfloat16, wmma::row_major> b_hi, b_lo;
                wmma::load_matrix_sync(b_hi, Bs_hi + (kk * 16) * LDB + wn + j * 16, LDB);
                wmma::load_matrix_sync(b_lo, Bs_lo + (kk * 16) * LDB + wn + j * 16, LDB);
#pragma unroll
                for (int i = 0; i < 2; i++) {
                    wmma::mma_sync(acc[i][j], a_hi[i], b_hi, acc[i][j]);
                    wmma::mma_sync(acc[i][j], a_hi[i], b_lo, acc[i][j]);
                    wmma::mma_sync(acc[i][j], a_lo[i], b_hi, acc[i][j]);
                }
            }
        }
        __syncthreads();
    }

    // epilogue
#pragma unroll
    for (int i = 0; i < 2; i++)
#pragma unroll
        for (int j = 0; j < 4; j++)
            wmma::store_matrix_sync(Cs + (wm + i * 16) * LDO + wn + j * 16,
                                    acc[i][j], LDO, wmma::mem_row_major);
    __syncthreads();

    {
        const int row = tid >> 1;
        const int c0  = (tid & 1) * 64;
        const int m   = bm0 + row;
        const float4* src = (const float4*)(Cs + row * LDO + c0);
#pragma unroll
        for (int u = 0; u < 16; u++) {
            float4 v = src[u];
            int n = bn0 + c0 + u * 4;
            v.x += bias[n + 0]; v.y += bias[n + 1];
            v.z += bias[n + 2]; v.w += bias[n + 3];
            if (SPLIT) {
                float f[4] = {v.x, v.y, v.z, v.w};
                __nv_bfloat16 h[4], l[4];
#pragma unroll
                for (int q = 0; q < 4; q++) {
                    h[q] = __float2bfloat16_rn(f[q]);
                    l[q] = __float2bfloat16_rn(f[q] - __bfloat162float(h[q]));
                }
                int bb = m >> 11, s = m & 2047;
                int hh = n >> 6,  dd = n & 63;
                size_t idx = ((((size_t)bb * NHEADS) + hh) * SEQ + s) * DK + dd;
                *(__nv_bfloat162*)&Ch[idx]     = __nv_bfloat162(h[0], h[1]);
                *(__nv_bfloat162*)&Ch[idx + 2] = __nv_bfloat162(h[2], h[3]);
                *(__nv_bfloat162*)&Cl[idx]     = __nv_bfloat162(l[0], l[1]);
                *(__nv_bfloat162*)&Cl[idx + 2] = __nv_bfloat162(l[2], l[3]);
            } else {
                *(float4*)&Cf[(size_t)m * GN + n] = v;
            }
        }
    }
}

// ---------------------------------------------------------------------------
// wmma flash attention, causal. Block: 256 thr / 8 warps, 64 q-rows, 64-key
// tiles. QK^T and PV via 3-pass hi/lo bf16 MMAs. Online softmax on a 64x64
// fp32 smem score tile; O accumulated in fp32 smem with per-tile rescale.
// Output written as bf16 hi/lo [B,S,D].
// ---------------------------------------------------------------------------
#define ALD   72     // bf16 tile leading dim
#define CLD   68     // f32 tile leading dim
#define AOFF_QH  0
#define AOFF_QL  (AOFF_QH + 64 * ALD * 2)
#define AOFF_KH  (AOFF_QL + 64 * ALD * 2)
#define AOFF_KL  (AOFF_KH + 64 * ALD * 2)
#define AOFF_VH  (AOFF_KL + 64 * ALD * 2)
#define AOFF_VL  (AOFF_VH + 64 * ALD * 2)
#define AOFF_PH  (AOFF_VL + 64 * ALD * 2)
#define AOFF_PL  (AOFF_PH + 64 * ALD * 2)
#define AOFF_SF  (AOFF_PL + 64 * ALD * 2)
#define AOFF_OA  (AOFF_SF + 64 * CLD * 4)
#define AOFF_M   (AOFF_OA + 64 * CLD * 4)
#define AOFF_L   (AOFF_M + 256)
#define AOFF_AL  (AOFF_L + 256)
#define AOFF_PM  (AOFF_AL + 256)
#define ATT_SMEM (AOFF_PM + 256)

__global__ __launch_bounds__(256)
void flash_attn_tc(const __nv_bfloat16* __restrict__ Qh, const __nv_bfloat16* __restrict__ Ql,
                   const __nv_bfloat16* __restrict__ Kh, const __nv_bfloat16* __restrict__ Kl,
                   const __nv_bfloat16* __restrict__ Vh, const __nv_bfloat16* __restrict__ Vl,
                   const float* __restrict__ pmask,
                   __nv_bfloat16* __restrict__ Oh, __nv_bfloat16* __restrict__ Ol)
{
    extern __shared__ char smem[];
    __nv_bfloat16* Qsh = (__nv_bfloat16*)(smem + AOFF_QH);
    __nv_bfloat16* Qsl = (__nv_bfloat16*)(smem + AOFF_QL);
    __nv_bfloat16* Ksh = (__nv_bfloat16*)(smem + AOFF_KH);
    __nv_bfloat16* Ksl = (__nv_bfloat16*)(smem + AOFF_KL);
    __nv_bfloat16* Vsh = (__nv_bfloat16*)(smem + AOFF_VH);
    __nv_bfloat16* Vsl = (__nv_bfloat16*)(smem + AOFF_VL);
    __nv_bfloat16* Psh = (__nv_bfloat16*)(smem + AOFF_PH);
    __nv_bfloat16* Psl = (__nv_bfloat16*)(smem + AOFF_PL);
    float* Sf  = (float*)(smem + AOFF_SF);
    float* Oa  = (float*)(smem + AOFF_OA);
    float* mst = (float*)(smem + AOFF_M);
    float* lst = (float*)(smem + AOFF_L);
    float* ast = (float*)(smem + AOFF_AL);
    float* pms = (float*)(smem + AOFF_PM);

    const int tid  = threadIdx.x;
    const int wid  = tid >> 5;
    const int row  = tid >> 2;          // 0..63 (for scalar phases)
    const int quad = tid & 3;
    const int q0   = blockIdx.x * 64;
    const int bh   = blockIdx.y;
    const int b    = bh >> 4;
    const int h    = bh & 15;
    const int wm   = (wid & 3) * 16;    // warp rows
    const int wn   = (wid >> 2) * 32;   // warp cols

    // load Q tile (once) + init
    {
        const size_t base = ((size_t)bh * SEQ + q0 + row) * DK + quad * 16;
        const uint4* sh = (const uint4*)(Qh + base);
        const uint4* sl = (const uint4*)(Ql + base);
        uint4* dh = (uint4*)(Qsh + row * ALD + quad * 16);
        uint4* dl = (uint4*)(Qsl + row * ALD + quad * 16);
        dh[0] = sh[0]; dh[1] = sh[1];
        dl[0] = sl[0]; dl[1] = sl[1];
    }
#pragma unroll
    for (int u = 0; u < 16; u++) Oa[row * CLD + quad * 16 + u] = 0.f;
    if (tid < 64) { mst[tid] = -1e30f; lst[tid] = 0.f; }

    const int ntiles = blockIdx.x + 1;
    for (int t = 0; t < ntiles; t++) {
        const int k0 = t * 64;
        // stage K/V hi/lo tiles
        {
            const size_t base = ((size_t)bh * SEQ + k0 + row) * DK + quad * 16;
            uint4* d0 = (uint4*)(Ksh + row * ALD + quad * 16);
            uint4* d1 = (uint4*)(Ksl + row * ALD + quad * 16);
            uint4* d2 = (uint4*)(Vsh + row * ALD + quad * 16);
            uint4* d3 = (uint4*)(Vsl + row * ALD + quad * 16);
            const uint4* s0 = (const uint4*)(Kh + base);
            const uint4* s1 = (const uint4*)(Kl + base);
            const uint4* s2 = (const uint4*)(Vh + base);
            const uint4* s3 = (const uint4*)(Vl + base);
            d0[0] = s0[0]; d0[1] = s0[1];
            d1[0] = s1[0]; d1[1] = s1[1];
            d2[0] = s2[0]; d2[1] = s2[1];
            d3[0] = s3[0]; d3[1] = s3[1];
        }
        if (tid < 64) pms[tid] = pmask[(size_t)b * SEQ + k0 + tid];
        __syncthreads();

        // ---- scores = Q @ K^T (hi/lo 3-pass), warp tile 16x32
        {
            wmma::fragment<wmma::accumulator, 16, 16, 16, float> sacc[2];
            wmma::fill_fragment(sacc[0], 0.f);
            wmma::fill_fragment(sacc[1], 0.f);
#pragma unroll
            for (int kk = 0; kk < 4; kk++) {
                wmma::fragment<wmma::matrix_a, 16, 16, 16, __nv_bfloat16, wmma::row_major> a_hi, a_lo;
                wmma::load_matrix_sync(a_hi, Qsh + wm * ALD + kk * 16, ALD);
                wmma::load_matrix_sync(a_lo, Qsl + wm * ALD + kk * 16, ALD);
#pragma unroll
                for (int j = 0; j < 2; j++) {
                    wmma::fragment<wmma::matrix_b, 16, 16, 16, __nv_bfloat16, wmma::col_major> b_hi, b_lo;
                    wmma::load_matrix_sync(b_hi, Ksh + (wn + j * 16) * ALD + kk * 16, ALD);
                    wmma::load_matrix_sync(b_lo, Ksl + (wn + j * 16) * ALD + kk * 16, ALD);
                    wmma::mma_sync(sacc[j], a_hi, b_hi, sacc[j]);
                    wmma::mma_sync(sacc[j], a_hi, b_lo, sacc[j]);
                    wmma::mma_sync(sacc[j], a_lo, b_hi, sacc[j]);
                }
            }
            wmma::store_matrix_sync(Sf + wm * CLD + wn,      sacc[0], CLD, wmma::mem_row_major);
            wmma::store_matrix_sync(Sf + wm * CLD + wn + 16, sacc[1], CLD, wmma::mem_row_major);
        }
        __syncthreads();

        // ---- softmax (quad of 4 lanes per row, 16 cols each)
        {
            float sv[16];
            float mloc = -1e30f;
            const int qi = q0 + row;
#pragma unroll
            for (int u = 0; u < 16; u++) {
                int c = quad * 16 + u;
                float s = Sf[row * CLD + c] * 0.125f + pms[c]
                        + ((k0 + c > qi) ? -1e9f : 0.f);
                sv[u] = s;
                mloc = fmaxf(mloc, s);
            }
            mloc = fmaxf(mloc, __shfl_xor_sync(0xffffffffu, mloc, 1));
            mloc = fmaxf(mloc, __shfl_xor_sync(0xffffffffu, mloc, 2));
            float mold = mst[row];
            float mnew = fmaxf(mold, mloc);
            float alpha = __expf(mold - mnew);
            float lsum = 0.f;
#pragma unroll
            for (int u = 0; u < 16; u++) {
                float p = __expf(sv[u] - mnew);
                lsum += p;
                __nv_bfloat16 ph = __float2bfloat16_rn(p);
                __nv_bfloat16 pl = __float2bfloat16_rn(p - __bfloat162float(ph));
                Psh[row * ALD + quad * 16 + u] = ph;
                Psl[row * ALD + quad * 16 + u] = pl;
            }
            lsum += __shfl_xor_sync(0xffffffffu, lsum, 1);
            lsum += __shfl_xor_sync(0xffffffffu, lsum, 2);
            if (quad == 0) {
                mst[row] = mnew;
                lst[row] = lst[row] * alpha + lsum;
                ast[row] = alpha;
            }
        }
        __syncthreads();

        // ---- PV = P @ V (hi/lo 3-pass), warp tile 16x32, into Sf (reuse)
        {
            wmma::fragment<wmma::accumulator, 16, 16, 16, float> oacc[2];
            wmma::fill_fragment(oacc[0], 0.f);
            wmma::fill_fragment(oacc[1], 0.f);
#pragma unroll
            for (int kk = 0; kk < 4; kk++) {
                wmma::fragment<wmma::matrix_a, 16, 16, 16, __nv_bfloat16, wmma::row_major> p_hi, p_lo;
                wmma::load_matrix_sync(p_hi, Psh + wm * ALD + kk * 16, ALD);
                wmma::load_matrix_sync(p_lo, Psl + wm * ALD + kk * 16, ALD);
#pragma unroll
                for (int j = 0; j < 2; j++) {
                    wmma::fragment<wmma::matrix_b, 16, 16, 16, __nv_bfloat16, wmma::row_major> v_hi, v_lo;
                    wmma::load_matrix_sync(v_hi, Vsh + (kk * 16) * ALD + wn + j * 16, ALD);
                    wmma::load_matrix_sync(v_lo, Vsl + (kk * 16) * ALD + wn + j * 16, ALD);
                    wmma::mma_sync(oacc[j], p_hi, v_hi, oacc[j]);
                    wmma::mma_sync(oacc[j], p_hi, v_lo, oacc[j]);
                    wmma::mma_sync(oacc[j], p_lo, v_hi, oacc[j]);
                }
            }
            wmma::store_matrix_sync(Sf + wm * CLD + wn,      oacc[0], CLD, wmma::mem_row_major);
            wmma::store_matrix_sync(Sf + wm * CLD + wn + 16, oacc[1], CLD, wmma::mem_row_major);
        }
        __syncthreads();

        // ---- O = O*alpha + PV
        {
            float alpha = ast[row];
#pragma unroll
            for (int u = 0; u < 16; u++) {
                int c = quad * 16 + u;
                Oa[row * CLD + c] = Oa[row * CLD + c] * alpha + Sf[row * CLD + c];
            }
        }
        __syncthreads();
    }

    // ---- epilogue: O / l, convert hi/lo, store [B,S,D]
    {
        float inv = 1.f / lst[row];
        size_t base = ((size_t)b * SEQ + q0 + row) * DMODEL + h * DK + quad * 16;
#pragma unroll
        for (int u = 0; u < 16; u += 2) {
            float v0 = Oa[row * CLD + quad * 16 + u]     * inv;
            float v1 = Oa[row * CLD + quad * 16 + u + 1] * inv;
            __nv_bfloat16 h0 = __float2bfloat16_rn(v0);
            __nv_bfloat16 h1 = __float2bfloat16_rn(v1);
            __nv_bfloat16 l0 = __float2bfloat16_rn(v0 - __bfloat162float(h0));
            __nv_bfloat16 l1 = __float2bfloat16_rn(v1 - __bfloat162float(h1));
            *(__nv_bfloat162*)&Oh[base + u] = __nv_bfloat162(h0, h1);
            *(__nv_bfloat162*)&Ol[base + u] = __nv_bfloat162(l0, l1);
        }
    }
}

// ---------------------------------------------------------------------------
// Launch. Inputs: 0 query, 1 key, 2 value, 3 padding_mask, 4 lookahead_mask,
// 5 w_q, 6 w_k, 7 w_v, 8 w_out, 9 b_q, 10 b_k, 11 b_v, 12 b_out, 13 n_heads
// ---------------------------------------------------------------------------
extern "C" void kernel_launch(void* const* d_in, const int* in_sizes, int n_in,
                              void* d_out, int out_size)
{
    const float* query = (const float*)d_in[0];
    const float* key   = (const float*)d_in[1];
    const float* value = (const float*)d_in[2];
    const float* pmask = (const float*)d_in[3];
    const float* w_q   = (const float*)d_in[5];
    const float* w_k   = (const float*)d_in[6];
    const float* w_v   = (const float*)d_in[7];
    const float* w_out = (const float*)d_in[8];
    const float* b_q   = (const float*)d_in[9];
    const float* b_k   = (const float*)d_in[10];
    const float* b_v   = (const float*)d_in[11];
    const float* b_out = (const float*)d_in[12];
    float* out = (float*)d_out;

    __nv_bfloat16 *aqh, *aql, *akh, *akl, *avh, *avl;
    __nv_bfloat16 *wqh, *wql, *wkh, *wkl, *wvh, *wvl, *woh, *wol;
    __nv_bfloat16 *qh, *ql, *kh, *kl, *vh, *vl, *oh, *ol;
    cudaGetSymbolAddress((void**)&aqh, g_aqh); cudaGetSymbolAddress((void**)&aql, g_aql);
    cudaGetSymbolAddress((void**)&akh, g_akh); cudaGetSymbolAddress((void**)&akl, g_akl);
    cudaGetSymbolAddress((void**)&avh, g_avh); cudaGetSymbolAddress((void**)&avl, g_avl);
    cudaGetSymbolAddress((void**)&wqh, g_wqh); cudaGetSymbolAddress((void**)&wql, g_wql);
    cudaGetSymbolAddress((void**)&wkh, g_wkh); cudaGetSymbolAddress((void**)&wkl, g_wkl);
    cudaGetSymbolAddress((void**)&wvh, g_wvh); cudaGetSymbolAddress((void**)&wvl, g_wvl);
    cudaGetSymbolAddress((void**)&woh, g_woh); cudaGetSymbolAddress((void**)&wol, g_wol);
    cudaGetSymbolAddress((void**)&qh,  g_qh);  cudaGetSymbolAddress((void**)&ql,  g_ql);
    cudaGetSymbolAddress((void**)&kh,  g_kh);  cudaGetSymbolAddress((void**)&kl,  g_kl);
    cudaGetSymbolAddress((void**)&vh,  g_vh);  cudaGetSymbolAddress((void**)&vl,  g_vl);
    cudaGetSymbolAddress((void**)&oh,  g_oh);  cudaGetSymbolAddress((void**)&ol,  g_ol);

    cudaFuncSetAttribute(gemm_tc<0>, cudaFuncAttributeMaxDynamicSharedMemorySize, GEMM_SMEM);
    cudaFuncSetAttribute(gemm_tc<1>, cudaFuncAttributeMaxDynamicSharedMemorySize, GEMM_SMEM);
    cudaFuncSetAttribute(flash_attn_tc, cudaFuncAttributeMaxDynamicSharedMemorySize, ATT_SMEM);

    // pre-convert activations + weights to bf16 hi/lo
    cvt_hilo<<<NELEM / 1024, 256>>>((const float4*)query, aqh, aql, NELEM / 4);
    cvt_hilo<<<NELEM / 1024, 256>>>((const float4*)key,   akh, akl, NELEM / 4);
    cvt_hilo<<<NELEM / 1024, 256>>>((const float4*)value, avh, avl, NELEM / 4);
    cvt_hilo<<<WELEM / 1024, 256>>>((const float4*)w_q,   wqh, wql, WELEM / 4);
    cvt_hilo<<<WELEM / 1024, 256>>>((const float4*)w_k,   wkh, wkl, WELEM / 4);
    cvt_hilo<<<WELEM / 1024, 256>>>((const float4*)w_v,   wvh, wvl, WELEM / 4);
    cvt_hilo<<<WELEM / 1024, 256>>>((const float4*)w_out, woh, wol, WELEM / 4);

    dim3 gproj(GN / 128, MROWS / 128);   // (8, 32)
    gemm_tc<1><<<gproj, 256, GEMM_SMEM>>>(aqh, aql, wqh, wql, b_q, nullptr, qh, ql);
    gemm_tc<1><<<gproj, 256, GEMM_SMEM>>>(akh, akl, wkh, wkl, b_k, nullptr, kh, kl);
    gemm_tc<1><<<gproj, 256, GEMM_SMEM>>>(avh, avl, wvh, wvl, b_v, nullptr, vh, vl);

    dim3 gattn(SEQ / 64, BATCH * NHEADS);    // (32, 32)
    flash_attn_tc<<<gattn, 256, ATT_SMEM>>>(qh, ql, kh, kl, vh, vl, pmask, oh, ol);

    gemm_tc<0><<<gproj, 256, GEMM_SMEM>>>(oh, ol, woh, wol, b_out, out, nullptr, nullptr);
}